// round 7
// baseline (speedup 1.0000x reference)
#include <cuda_runtime.h>
#include <cuda_bf16.h>
#include <cuda_fp16.h>
#include <cstdint>

// Problem constants
#define NB   8
#define NN   8192
#define CIN  64
#define COUT 128
#define KNB  16
#define MM   16
#define NPTS (NB*NN)            // 65536
#define AGGK (CIN*MM)           // 1024

// -------- device scratch --------
__device__ __half g_WpTh[(size_t)COUT * AGGK];   // weight^T [n][j], fp16 (j bijection below)
__device__ float  g_A1[32*3];
__device__ float  g_c1[32];

// j bijection: c = mt*16 + ih*8 + g ; m = nt*8 + t4*2 + b
// u = mt*128 + (ih*2+nt)*32 + g*4 + t4 ; j = 2u + b

// ============================================================
// PTX helpers (generic-target-safe: cp.async, mma.sync, ldmatrix)
// ============================================================
__device__ __forceinline__ uint32_t smem_u32(const void* p) {
    uint32_t a;
    asm("{ .reg .u64 t; cvta.to.shared.u64 t, %1; cvt.u32.u64 %0, t; }" : "=r"(a) : "l"(p));
    return a;
}
__device__ __forceinline__ uint32_t to_tf32u(float x) {
    uint32_t u;
    asm("cvt.rna.tf32.f32 %0, %1;" : "=r"(u) : "f"(x));
    return u;
}
#define CP_ASYNC16(dst, src) \
    asm volatile("cp.async.cg.shared.global [%0], [%1], 16;" :: "r"(dst), "l"(src) : "memory")
#define CP_COMMIT() asm volatile("cp.async.commit_group;" ::: "memory")
#define CP_WAIT0()  asm volatile("cp.async.wait_group 0;" ::: "memory")

__device__ __forceinline__ void ldsm_x4(uint32_t& r0, uint32_t& r1, uint32_t& r2, uint32_t& r3,
                                        uint32_t addr) {
    asm volatile("ldmatrix.sync.aligned.m8n8.x4.shared.b16 {%0,%1,%2,%3}, [%4];"
                 : "=r"(r0), "=r"(r1), "=r"(r2), "=r"(r3) : "r"(addr));
}
__device__ __forceinline__ void mma_tf32(float c[4], const uint32_t a[4], const uint32_t b[2]) {
    asm volatile(
        "mma.sync.aligned.m16n8k8.row.col.f32.tf32.tf32.f32 "
        "{%0,%1,%2,%3}, {%4,%5,%6,%7}, {%8,%9}, {%0,%1,%2,%3};"
        : "+f"(c[0]), "+f"(c[1]), "+f"(c[2]), "+f"(c[3])
        : "r"(a[0]), "r"(a[1]), "r"(a[2]), "r"(a[3]), "r"(b[0]), "r"(b[1]));
}
__device__ __forceinline__ void mma_f16(float c[4], const uint32_t a[4], const uint32_t b[2]) {
    asm volatile(
        "mma.sync.aligned.m16n8k16.row.col.f32.f16.f16.f32 "
        "{%0,%1,%2,%3}, {%4,%5,%6,%7}, {%8,%9}, {%0,%1,%2,%3};"
        : "+f"(c[0]), "+f"(c[1]), "+f"(c[2]), "+f"(c[3])
        : "r"(a[0]), "r"(a[1]), "r"(a[2]), "r"(a[3]), "r"(b[0]), "r"(b[1]));
}

// ============================================================
// Prep 1: collapse MLP layer 1 (affine in rel coords).
// ============================================================
__global__ void prep_kernel(const float* __restrict__ l1_w,
                            const float* __restrict__ l1_b,
                            const float* __restrict__ centers)
{
    int o = threadIdx.x;
    if (o >= 32) return;
    float a0 = 0.f, a1 = 0.f, a2 = 0.f;
    float c = l1_b[o];
    #pragma unroll
    for (int m = 0; m < MM; m++) {
        float w0 = l1_w[o*48 + 0*16 + m];
        float w1 = l1_w[o*48 + 1*16 + m];
        float w2 = l1_w[o*48 + 2*16 + m];
        a0 += w0; a1 += w1; a2 += w2;
        c -= w0 * centers[0*16 + m];
        c -= w1 * centers[1*16 + m];
        c -= w2 * centers[2*16 + m];
    }
    g_A1[o*3+0] = a0; g_A1[o*3+1] = a1; g_A1[o*3+2] = a2;
    g_c1[o] = c;
}

// ============================================================
// Prep 2: weight[(c*16+m)*128 + n] -> g_WpTh[n*1024 + j(c,m)], fp16
// ============================================================
__global__ void permw_kernel(const float* __restrict__ weight)
{
    int e = blockIdx.x * blockDim.x + threadIdx.x;
    if (e >= AGGK * COUT) return;
    int n  = e & 127;
    int cm = e >> 7;
    int m  = cm & 15;
    int c  = cm >> 4;
    int gg = c & 7, ih = (c >> 3) & 1, mt = c >> 4;
    int nt = m >> 3, t4 = (m >> 1) & 3, b = m & 1;
    int u  = mt*128 + (ih*2 + nt)*32 + gg*4 + t4;
    g_WpTh[(size_t)n*AGGK + 2*u + b] = __float2half_rn(weight[e]);
}

// ============================================================
// Fused kernel: MLP + agg(tf32 mma) -> smem -> GEMM(fp16 mma) -> out
// CTA = 128 points = one GEMM M-tile. 256 threads, 8 warps.
// K processed in 4 tranches of 256 halves; A produced into smem,
// B streamed from g_WpTh via cp.async (overlapped with produce).
// ============================================================
#define FPTS 128
#define FTHR 256
#define PA   264    // sA/sB pitch (halves): 528B rows -> ldmatrix conflict-free
#define PD   18     // sDh per-k pitch (halves)

#define OFF_A 0
#define OFF_B (OFF_A + 128*PA*2)            // 67584
#define OFF_D (OFF_B + 128*PA*2)            // 135168
#define OFF_I (OFF_D + 128*288*2)           // 208896
#define OFF_W (OFF_I + 128*KNB*4)           // 217088
#define FUSED_SMEM (OFF_W + 1056*4)         // 221312

__global__ __launch_bounds__(FTHR)
void fused_kernel(const float* __restrict__ features,
                  const float* __restrict__ input_pts,
                  const float* __restrict__ output_pts,
                  const int*   __restrict__ indices,
                  const float* __restrict__ l2_w, const float* __restrict__ l2_b,
                  const float* __restrict__ l3_w, const float* __restrict__ l3_b,
                  const float* __restrict__ bias, float* __restrict__ out)
{
    extern __shared__ __align__(16) char smem[];
    __half* sA  = (__half*)(smem + OFF_A);
    __half* sDh = (__half*)(smem + OFF_D);
    int*    sI  = (int*)   (smem + OFF_I);
    float*  sw  = (float*) (smem + OFF_W);
    float* sA1 = sw;        float* sC1 = sw + 96;
    float* sW2 = sw + 128;  float* sB2 = sw + 640;
    float* sW3 = sw + 656;  float* sB3 = sw + 912;
    float* sbias = sw + 928;

    const int tid  = threadIdx.x;
    const int lane = tid & 31;
    const int w    = tid >> 5;
    const int g    = lane >> 2;
    const int t4   = lane & 3;
    const int q    = lane >> 4;
    const int k    = lane & 15;
    const int p0   = blockIdx.x * FPTS;
    const int b    = p0 >> 13;
    const float* __restrict__ fb = features + (size_t)b * NN * CIN;
    const uint32_t smb = smem_u32(smem);

    // stage small weights
    if (tid < 96)  sA1[tid] = g_A1[tid];
    if (tid >= 96 && tid < 128) sC1[tid-96] = g_c1[tid-96];
    if (tid < 16)  { sB2[tid] = l2_b[tid]; sB3[tid] = l3_b[tid]; }
    #pragma unroll
    for (int i = tid; i < 512; i += FTHR) sW2[i] = l2_w[i];
    if (tid < 256) sW3[tid] = l3_w[tid];
    if (tid < 128) sbias[tid] = bias[tid];

    // B tranche loader: 64KB = 4096 16B atoms / 256 thr = 16 each
    auto loadB = [&](int mt) {
        #pragma unroll
        for (int i = 0; i < 16; i++) {
            const int a  = tid + i*FTHR;
            const int n  = a >> 5;
            const int ca = a & 31;
            CP_ASYNC16(smb + OFF_B + (uint32_t)(n*PA + ca*8)*2,
                       g_WpTh + (size_t)n*AGGK + mt*256 + ca*8);
        }
        CP_COMMIT();
    };
    loadB(0);                 // overlaps with MLP stage

    __syncthreads();          // weights visible

    // ---- MLP stage: warp w owns points w*16..w*16+15; 8 rounds of 2 pts ----
    for (int r = 0; r < 8; r++) {
        const int lp  = w*16 + r*2 + q;
        const int p   = p0 + lp;
        const int idx = indices[p*KNB + k];
        sI[lp*KNB + k] = idx;
        const float ox = output_pts[p*3+0];
        const float oy = output_pts[p*3+1];
        const float oz = output_pts[p*3+2];
        const float* ip = input_pts + (size_t)(b*NN + idx) * 3;
        const float rx = ip[0] - ox, ry = ip[1] - oy, rz = ip[2] - oz;

        float h1[32];
        #pragma unroll
        for (int o = 0; o < 32; o++) {
            float v = sC1[o] + sA1[o*3+0]*rx + sA1[o*3+1]*ry + sA1[o*3+2]*rz;
            h1[o] = fmaxf(v, 0.f);
        }
        float h2[16];
        #pragma unroll
        for (int o = 0; o < 16; o++) {
            float v = sB2[o];
            #pragma unroll
            for (int i4 = 0; i4 < 8; i4++) {
                float4 wv = *(const float4*)&sW2[o*32 + i4*4];
                v += wv.x*h1[i4*4+0] + wv.y*h1[i4*4+1]
                   + wv.z*h1[i4*4+2] + wv.w*h1[i4*4+3];
            }
            h2[o] = fmaxf(v, 0.f);
        }
        __half* drow = sDh + lp*288 + k*PD;
        #pragma unroll
        for (int o = 0; o < 16; o++) {
            float v = sB3[o];
            #pragma unroll
            for (int i4 = 0; i4 < 4; i4++) {
                float4 wv = *(const float4*)&sW3[o*16 + i4*4];
                v += wv.x*h2[i4*4+0] + wv.y*h2[i4*4+1]
                   + wv.z*h2[i4*4+2] + wv.w*h2[i4*4+3];
            }
            drow[o] = __float2half_rn(fmaxf(v, 0.f));
        }
    }
    __syncwarp();             // sDh/sI are warp-local; no CTA sync needed

    // ---- GEMM state ----
    const int m0 = (w >> 2) * 64;
    const int n0 = (w & 3) * 32;
    const int a_r  = (lane & 7) + ((lane >> 3) & 1) * 8;
    const int a_ka = lane >> 4;
    const int b_r  = (lane & 7) + (lane >> 4) * 8;
    const int b_ka = (lane >> 3) & 1;

    float acc[4][4][4];
    #pragma unroll
    for (int mf = 0; mf < 4; mf++)
        #pragma unroll
        for (int nf = 0; nf < 4; nf++)
            #pragma unroll
            for (int i = 0; i < 4; i++) acc[mf][nf][i] = 0.f;

    // ---- tranche loop ----
    for (int mt = 0; mt < 4; mt++) {
        // produce A tranche: this warp's 16 points
        for (int i = 0; i < 16; i++) {
            const int lp = w*16 + i;
            float pa[2][4];
            #pragma unroll
            for (int nt = 0; nt < 2; nt++)
                #pragma unroll
                for (int j = 0; j < 4; j++) pa[nt][j] = 0.f;

            #pragma unroll
            for (int kc = 0; kc < 2; kc++) {
                const int k0 = kc*8 + t4;
                const float* r0 = fb + (size_t)sI[lp*KNB + k0    ] * CIN;
                const float* r1 = fb + (size_t)sI[lp*KNB + k0 + 4] * CIN;

                uint32_t bfr[2][2];
                #pragma unroll
                for (int nt = 0; nt < 2; nt++) {
                    bfr[nt][0] = __float_as_uint(
                        __half2float(sDh[lp*288 + (k0    )*PD + nt*8 + g]));
                    bfr[nt][1] = __float_as_uint(
                        __half2float(sDh[lp*288 + (k0 + 4)*PD + nt*8 + g]));
                }
                uint32_t a[4];
                a[0] = to_tf32u(r0[mt*16 + g    ]);
                a[1] = to_tf32u(r0[mt*16 + g + 8]);
                a[2] = to_tf32u(r1[mt*16 + g    ]);
                a[3] = to_tf32u(r1[mt*16 + g + 8]);

                mma_tf32(pa[0], a, bfr[0]);
                mma_tf32(pa[1], a, bfr[1]);
            }
            // store tranche fragments: local u' = (ih*2+nt)*32 + lane
            __half2* arow = (__half2*)(sA + lp*PA);
            #pragma unroll
            for (int nt = 0; nt < 2; nt++) {
                arow[(0*2 + nt)*32 + lane] = __floats2half2_rn(pa[nt][0], pa[nt][1]);
                arow[(1*2 + nt)*32 + lane] = __floats2half2_rn(pa[nt][2], pa[nt][3]);
            }
        }

        CP_WAIT0();           // own B copies complete
        __syncthreads();      // sA + sB visible to all

        // GEMM over this tranche: 16 x k16 steps
        #pragma unroll 4
        for (int ks = 0; ks < 16; ks++) {
            uint32_t a[4][4], bb[4][2];
            #pragma unroll
            for (int mf = 0; mf < 4; mf++) {
                uint32_t addr = smb + OFF_A
                    + (uint32_t)((m0 + mf*16 + a_r)*PA + (ks*2 + a_ka)*8) * 2;
                ldsm_x4(a[mf][0], a[mf][1], a[mf][2], a[mf][3], addr);
            }
            #pragma unroll
            for (int np = 0; np < 2; np++) {
                uint32_t addr = smb + OFF_B
                    + (uint32_t)((n0 + np*16 + b_r)*PA + (ks*2 + b_ka)*8) * 2;
                ldsm_x4(bb[np*2][0], bb[np*2][1], bb[np*2+1][0], bb[np*2+1][1], addr);
            }
            #pragma unroll
            for (int mf = 0; mf < 4; mf++)
                #pragma unroll
                for (int nf = 0; nf < 4; nf++)
                    mma_f16(acc[mf][nf], a[mf], bb[nf]);
        }
        __syncthreads();      // sA/sB free for next tranche

        if (mt < 3) loadB(mt + 1);   // overlaps next produce
    }

    // ---- epilogue: /K + bias ----
    const float inv_k = 1.0f / (float)KNB;
    #pragma unroll
    for (int mf = 0; mf < 4; mf++) {
        const int row = p0 + m0 + mf*16 + g;
        #pragma unroll
        for (int nf = 0; nf < 4; nf++) {
            const int col = n0 + nf*8 + t4*2;
            const float b0 = sbias[col], b1 = sbias[col+1];
            float2 v0 = make_float2(acc[mf][nf][0]*inv_k + b0, acc[mf][nf][1]*inv_k + b1);
            float2 v1 = make_float2(acc[mf][nf][2]*inv_k + b0, acc[mf][nf][3]*inv_k + b1);
            *(float2*)(out + (size_t)row*COUT + col)     = v0;
            *(float2*)(out + (size_t)(row+8)*COUT + col) = v1;
        }
    }
}

// ============================================================
// Copy output_pts into the tail of the flattened tuple output.
// ============================================================
__global__ void copy_pts_kernel(const float* __restrict__ src, float* __restrict__ dst)
{
    int i = blockIdx.x * blockDim.x + threadIdx.x;
    const int n4 = (NPTS * 3) / 4;
    if (i < n4) ((float4*)dst)[i] = ((const float4*)src)[i];
}

// ============================================================
extern "C" void kernel_launch(void* const* d_in, const int* in_sizes, int n_in,
                              void* d_out, int out_size)
{
    const float* features   = (const float*)d_in[0];
    const float* input_pts  = (const float*)d_in[1];
    const float* output_pts = (const float*)d_in[2];
    const int*   indices    = (const int*)  d_in[3];
    const float* centers    = (const float*)d_in[4];
    const float* weight     = (const float*)d_in[5];
    const float* bias       = (const float*)d_in[6];
    const float* l1_w       = (const float*)d_in[7];
    const float* l1_b       = (const float*)d_in[8];
    const float* l2_w       = (const float*)d_in[9];
    const float* l2_b       = (const float*)d_in[10];
    const float* l3_w       = (const float*)d_in[11];
    const float* l3_b       = (const float*)d_in[12];

    float* out = (float*)d_out;

    cudaFuncSetAttribute(fused_kernel,
                         cudaFuncAttributeMaxDynamicSharedMemorySize, FUSED_SMEM);

    prep_kernel<<<1, 32>>>(l1_w, l1_b, centers);
    permw_kernel<<<(AGGK*COUT + 255)/256, 256>>>(weight);
    fused_kernel<<<NPTS/FPTS, FTHR, FUSED_SMEM>>>(features, input_pts, output_pts,
                                                  indices, l2_w, l2_b, l3_w, l3_b,
                                                  bias, out);

    if (out_size >= NPTS*COUT + NPTS*3) {
        copy_pts_kernel<<<(NPTS*3/4 + 255)/256, 256>>>(output_pts, out + (size_t)NPTS*COUT);
    }
}

// round 8
// speedup vs baseline: 1.2255x; 1.2255x over previous
#include <cuda_runtime.h>
#include <cuda_bf16.h>
#include <cuda_fp16.h>
#include <cstdint>

// Problem constants
#define NB   8
#define NN   8192
#define CIN  64
#define COUT 128
#define KNB  16
#define MM   16
#define NPTS (NB*NN)            // 65536
#define AGGK (CIN*MM)           // 1024

// -------- device scratch --------
__device__ __half g_aggh[(size_t)NPTS * AGGK];   // 134 MB, [p][j], fp16
__device__ __half g_WpTh[(size_t)COUT * AGGK];   // weight^T [n][j], fp16
__device__ float  g_A1[32*3];
__device__ float  g_c1[32];

// j bijection: c = mt*16 + ih*8 + g ; m = nt*8 + t4*2 + b
// u = ((mt*2+ih)*2 + nt)*32 + g*4 + t4 ; j = 2u + b

// ============================================================
// PTX helpers
// ============================================================
__device__ __forceinline__ uint32_t smem_u32(const void* p) {
    uint32_t a;
    asm("{ .reg .u64 t; cvta.to.shared.u64 t, %1; cvt.u32.u64 %0, t; }" : "=r"(a) : "l"(p));
    return a;
}
__device__ __forceinline__ uint32_t to_tf32u(float x) {
    uint32_t u;
    asm("cvt.rna.tf32.f32 %0, %1;" : "=r"(u) : "f"(x));
    return u;
}
__device__ __forceinline__ float to_tf32f(float x) {
    uint32_t u;
    asm("cvt.rna.tf32.f32 %0, %1;" : "=r"(u) : "f"(x));
    return __uint_as_float(u);
}
#define CP_ASYNC16(dst, src) \
    asm volatile("cp.async.cg.shared.global [%0], [%1], 16;" :: "r"(dst), "l"(src) : "memory")
#define CP_COMMIT() asm volatile("cp.async.commit_group;" ::: "memory")
#define CP_WAIT1()  asm volatile("cp.async.wait_group 1;" ::: "memory")
#define CP_WAIT0()  asm volatile("cp.async.wait_group 0;" ::: "memory")

__device__ __forceinline__ void ldsm_x4(uint32_t& r0, uint32_t& r1, uint32_t& r2, uint32_t& r3,
                                        uint32_t addr) {
    asm volatile("ldmatrix.sync.aligned.m8n8.x4.shared.b16 {%0,%1,%2,%3}, [%4];"
                 : "=r"(r0), "=r"(r1), "=r"(r2), "=r"(r3) : "r"(addr));
}
__device__ __forceinline__ void mma_tf32(float c[4], const uint32_t a[4], const uint32_t b[2]) {
    asm volatile(
        "mma.sync.aligned.m16n8k8.row.col.f32.tf32.tf32.f32 "
        "{%0,%1,%2,%3}, {%4,%5,%6,%7}, {%8,%9}, {%0,%1,%2,%3};"
        : "+f"(c[0]), "+f"(c[1]), "+f"(c[2]), "+f"(c[3])
        : "r"(a[0]), "r"(a[1]), "r"(a[2]), "r"(a[3]), "r"(b[0]), "r"(b[1]));
}
__device__ __forceinline__ void mma_f16(float c[4], const uint32_t a[4], const uint32_t b[2]) {
    asm volatile(
        "mma.sync.aligned.m16n8k16.row.col.f32.f16.f16.f32 "
        "{%0,%1,%2,%3}, {%4,%5,%6,%7}, {%8,%9}, {%0,%1,%2,%3};"
        : "+f"(c[0]), "+f"(c[1]), "+f"(c[2]), "+f"(c[3])
        : "r"(a[0]), "r"(a[1]), "r"(a[2]), "r"(a[3]), "r"(b[0]), "r"(b[1]));
}

// ============================================================
// Prep 1: collapse MLP layer 1 (affine in rel coords).
// ============================================================
__global__ void prep_kernel(const float* __restrict__ l1_w,
                            const float* __restrict__ l1_b,
                            const float* __restrict__ centers)
{
    int o = threadIdx.x;
    if (o >= 32) return;
    float a0 = 0.f, a1 = 0.f, a2 = 0.f;
    float c = l1_b[o];
    #pragma unroll
    for (int m = 0; m < MM; m++) {
        float w0 = l1_w[o*48 + 0*16 + m];
        float w1 = l1_w[o*48 + 1*16 + m];
        float w2 = l1_w[o*48 + 2*16 + m];
        a0 += w0; a1 += w1; a2 += w2;
        c -= w0 * centers[0*16 + m];
        c -= w1 * centers[1*16 + m];
        c -= w2 * centers[2*16 + m];
    }
    g_A1[o*3+0] = a0; g_A1[o*3+1] = a1; g_A1[o*3+2] = a2;
    g_c1[o] = c;
}

// ============================================================
// Prep 2: weight -> g_WpTh[n*1024 + j(c,m)], fp16
// ============================================================
__global__ void permw_kernel(const float* __restrict__ weight)
{
    int e = blockIdx.x * blockDim.x + threadIdx.x;
    if (e >= AGGK * COUT) return;
    int n  = e & 127;
    int cm = e >> 7;
    int m  = cm & 15;
    int c  = cm >> 4;
    int gg = c & 7, ih = (c >> 3) & 1, mt = c >> 4;
    int nt = m >> 3, t4 = (m >> 1) & 3, b = m & 1;
    int u  = ((mt*2 + ih)*2 + nt)*32 + gg*4 + t4;
    g_WpTh[(size_t)n*AGGK + 2*u + b] = __float2half_rn(weight[e]);
}

// ============================================================
// Kernel A (v3): MLP layers 2-3 on tensor cores.
// 1 warp = 2 points = 32 samples. L1 in FFMA -> sH1; L2 = 32x16x32
// tf32 warp-GEMM -> sH2; L3 = 32x16x16 -> sD; phase3 as R6.
// ============================================================
#define PH1 33
#define PH2 18
#define PDD 18

__global__ __launch_bounds__(128)
void agg_kernel(const float* __restrict__ features,
                const float* __restrict__ input_pts,
                const float* __restrict__ output_pts,
                const int*   __restrict__ indices,
                const float* __restrict__ l2_w, const float* __restrict__ l2_b,
                const float* __restrict__ l3_w, const float* __restrict__ l3_b)
{
    __shared__ __align__(16) float sA1[96];
    __shared__ __align__(16) float sC1[32];
    __shared__ __align__(16) float sW2T[32*17];   // [f][o], tf32-rounded
    __shared__ __align__(16) float sB2[16];
    __shared__ __align__(16) float sW3T[16*17];   // [f][o], tf32-rounded
    __shared__ __align__(16) float sB3[16];
    __shared__ __align__(8) float sH1[4][32*PH1];
    __shared__ __align__(8) float sH2[4][32*PH2];
    __shared__ __align__(8) float sD [4][32*PDD];
    __shared__ int sI[4][2][KNB];

    const int tid = threadIdx.x;

    if (tid < 96)  sA1[tid] = g_A1[tid];
    if (tid < 32)  sC1[tid] = g_c1[tid];
    if (tid < 16)  { sB2[tid] = l2_b[tid]; sB3[tid] = l3_b[tid]; }
    for (int i = tid; i < 512; i += 128) {
        int o = i & 15, f = i >> 4;
        sW2T[f*17 + o] = to_tf32f(l2_w[o*32 + f]);
    }
    for (int i = tid; i < 256; i += 128) {
        int o = i & 15, f = i >> 4;
        sW3T[f*17 + o] = to_tf32f(l3_w[o*16 + f]);
    }
    __syncthreads();

    const int w     = tid >> 5;
    const int lane  = tid & 31;
    const int g     = lane >> 2;
    const int t4    = lane & 3;
    const int q     = lane >> 4;
    const int k     = lane & 15;
    const int pbase = blockIdx.x * 8 + w * 2;
    const int b     = pbase >> 13;
    const float* __restrict__ fb = features + (size_t)b * NN * CIN;

    float* H1 = sH1[w];
    float* H2 = sH2[w];
    float* Dd = sD[w];

    // ---- layer 1 (FFMA): sample s = lane ----
    {
        const int p   = pbase + q;
        const int idx = indices[p*KNB + k];
        sI[w][q][k] = idx;
        const float ox = output_pts[p*3+0];
        const float oy = output_pts[p*3+1];
        const float oz = output_pts[p*3+2];
        const float* ip = input_pts + (size_t)(b*NN + idx) * 3;
        const float rx = ip[0] - ox, ry = ip[1] - oy, rz = ip[2] - oz;

        #pragma unroll
        for (int o = 0; o < 32; o++) {
            float v = sC1[o] + sA1[o*3+0]*rx + sA1[o*3+1]*ry + sA1[o*3+2]*rz;
            H1[lane*PH1 + o] = fmaxf(v, 0.f);   // banks (lane+o)%32: conflict-free
        }
    }
    __syncwarp();

    // ---- layer 2: H2[32,16] = relu(H1[32,32] @ W2T + b2), tf32 mma ----
    {
        float c2[2][2][4];
        #pragma unroll
        for (int mt = 0; mt < 2; mt++)
            #pragma unroll
            for (int nt = 0; nt < 2; nt++)
                #pragma unroll
                for (int i = 0; i < 4; i++) c2[mt][nt][i] = 0.f;

        #pragma unroll
        for (int kc = 0; kc < 4; kc++) {
            uint32_t a[2][4];
            #pragma unroll
            for (int mt = 0; mt < 2; mt++) {
                a[mt][0] = to_tf32u(H1[(mt*16 + g    )*PH1 + kc*8 + t4    ]);
                a[mt][1] = to_tf32u(H1[(mt*16 + g + 8)*PH1 + kc*8 + t4    ]);
                a[mt][2] = to_tf32u(H1[(mt*16 + g    )*PH1 + kc*8 + t4 + 4]);
                a[mt][3] = to_tf32u(H1[(mt*16 + g + 8)*PH1 + kc*8 + t4 + 4]);
            }
            uint32_t bb[2][2];
            #pragma unroll
            for (int nt = 0; nt < 2; nt++) {
                bb[nt][0] = __float_as_uint(sW2T[(kc*8 + t4    )*17 + nt*8 + g]);
                bb[nt][1] = __float_as_uint(sW2T[(kc*8 + t4 + 4)*17 + nt*8 + g]);
            }
            #pragma unroll
            for (int mt = 0; mt < 2; mt++)
                #pragma unroll
                for (int nt = 0; nt < 2; nt++)
                    mma_tf32(c2[mt][nt], a[mt], bb[nt]);
        }
        #pragma unroll
        for (int nt = 0; nt < 2; nt++) {
            const float b0 = sB2[nt*8 + t4*2], b1 = sB2[nt*8 + t4*2 + 1];
            #pragma unroll
            for (int mt = 0; mt < 2; mt++) {
                float2 v0 = make_float2(fmaxf(c2[mt][nt][0] + b0, 0.f),
                                        fmaxf(c2[mt][nt][1] + b1, 0.f));
                float2 v1 = make_float2(fmaxf(c2[mt][nt][2] + b0, 0.f),
                                        fmaxf(c2[mt][nt][3] + b1, 0.f));
                *(float2*)&H2[(mt*16 + g    )*PH2 + nt*8 + t4*2] = v0;
                *(float2*)&H2[(mt*16 + g + 8)*PH2 + nt*8 + t4*2] = v1;
            }
        }
    }
    __syncwarp();

    // ---- layer 3: D[32,16] = relu(H2[32,16] @ W3T + b3), tf32 mma ----
    {
        float c3[2][2][4];
        #pragma unroll
        for (int mt = 0; mt < 2; mt++)
            #pragma unroll
            for (int nt = 0; nt < 2; nt++)
                #pragma unroll
                for (int i = 0; i < 4; i++) c3[mt][nt][i] = 0.f;

        #pragma unroll
        for (int kc = 0; kc < 2; kc++) {
            uint32_t a[2][4];
            #pragma unroll
            for (int mt = 0; mt < 2; mt++) {
                a[mt][0] = to_tf32u(H2[(mt*16 + g    )*PH2 + kc*8 + t4    ]);
                a[mt][1] = to_tf32u(H2[(mt*16 + g + 8)*PH2 + kc*8 + t4    ]);
                a[mt][2] = to_tf32u(H2[(mt*16 + g    )*PH2 + kc*8 + t4 + 4]);
                a[mt][3] = to_tf32u(H2[(mt*16 + g + 8)*PH2 + kc*8 + t4 + 4]);
            }
            uint32_t bb[2][2];
            #pragma unroll
            for (int nt = 0; nt < 2; nt++) {
                bb[nt][0] = __float_as_uint(sW3T[(kc*8 + t4    )*17 + nt*8 + g]);
                bb[nt][1] = __float_as_uint(sW3T[(kc*8 + t4 + 4)*17 + nt*8 + g]);
            }
            #pragma unroll
            for (int mt = 0; mt < 2; mt++)
                #pragma unroll
                for (int nt = 0; nt < 2; nt++)
                    mma_tf32(c3[mt][nt], a[mt], bb[nt]);
        }
        #pragma unroll
        for (int nt = 0; nt < 2; nt++) {
            const float b0 = sB3[nt*8 + t4*2], b1 = sB3[nt*8 + t4*2 + 1];
            #pragma unroll
            for (int mt = 0; mt < 2; mt++) {
                float2 v0 = make_float2(fmaxf(c3[mt][nt][0] + b0, 0.f),
                                        fmaxf(c3[mt][nt][1] + b1, 0.f));
                float2 v1 = make_float2(fmaxf(c3[mt][nt][2] + b0, 0.f),
                                        fmaxf(c3[mt][nt][3] + b1, 0.f));
                *(float2*)&Dd[(mt*16 + g    )*PDD + nt*8 + t4*2] = v0;
                *(float2*)&Dd[(mt*16 + g + 8)*PDD + nt*8 + t4*2] = v1;
            }
        }
    }
    __syncwarp();

    // ---- phase 3: per point, S = F^T(64x16) @ D(16x16), A gathered from global ----
    #pragma unroll
    for (int qq = 0; qq < 2; qq++) {
        float acc[4][2][4];
        #pragma unroll
        for (int mt = 0; mt < 4; mt++)
            #pragma unroll
            for (int nt = 0; nt < 2; nt++)
                #pragma unroll
                for (int i = 0; i < 4; i++) acc[mt][nt][i] = 0.f;

        #pragma unroll
        for (int kc = 0; kc < 2; kc++) {
            const int k0 = kc*8 + t4;
            const float* r0 = fb + (size_t)sI[w][qq][k0    ] * CIN;
            const float* r1 = fb + (size_t)sI[w][qq][k0 + 4] * CIN;

            uint32_t bfr[2][2];
            #pragma unroll
            for (int nt = 0; nt < 2; nt++) {
                bfr[nt][0] = to_tf32u(Dd[(qq*16 + k0    )*PDD + nt*8 + g]);
                bfr[nt][1] = to_tf32u(Dd[(qq*16 + k0 + 4)*PDD + nt*8 + g]);
            }

            uint32_t a[4][4];
            #pragma unroll
            for (int mt = 0; mt < 4; mt++) {
                a[mt][0] = to_tf32u(r0[mt*16 + g    ]);
                a[mt][1] = to_tf32u(r0[mt*16 + g + 8]);
                a[mt][2] = to_tf32u(r1[mt*16 + g    ]);
                a[mt][3] = to_tf32u(r1[mt*16 + g + 8]);
            }

            #pragma unroll
            for (int mt = 0; mt < 4; mt++) {
                mma_tf32(acc[mt][0], a[mt], bfr[0]);
                mma_tf32(acc[mt][1], a[mt], bfr[1]);
            }
        }

        __half2* orow = (__half2*)(g_aggh + (size_t)(pbase + qq) * AGGK);
        #pragma unroll
        for (int mt = 0; mt < 4; mt++) {
            #pragma unroll
            for (int nt = 0; nt < 2; nt++) {
                const int u0 = ((mt*2 + 0)*2 + nt)*32 + lane;
                const int u1 = ((mt*2 + 1)*2 + nt)*32 + lane;
                orow[u0] = __floats2half2_rn(acc[mt][nt][0], acc[mt][nt][1]);
                orow[u1] = __floats2half2_rn(acc[mt][nt][2], acc[mt][nt][3]);
            }
        }
    }
}

// ============================================================
// Kernel B: fp16 mma GEMM, 2-stage double buffer -> 2-3 CTAs/SM.
// ============================================================
#define GBK    64
#define HPITCH 72
#define HTSZ   (128*HPITCH*2)       // 18432 B
#define NCH    (AGGK/GBK)           // 16
#define GEMM_SMEM (2*2*HTSZ + 512)  // 74240

__global__ __launch_bounds__(256)
void gemm_mma_kernel(const float* __restrict__ bias, float* __restrict__ out)
{
    extern __shared__ __align__(16) char smem[];
    float* sbias = (float*)(smem + 2*2*HTSZ);

    const int tid  = threadIdx.x;
    const int lane = tid & 31;
    const int warp = tid >> 5;
    const int g    = lane >> 2;
    const int t4   = lane & 3;
    const int m0   = (warp >> 2) * 64;
    const int n0   = (warp & 3) * 32;
    const int p0   = blockIdx.x * 128;

    if (tid < COUT) sbias[tid] = bias[tid];

    const uint32_t smb = smem_u32(smem);
    const __half* gA = g_aggh + (size_t)p0 * AGGK;
    const __half* gB = g_WpTh;

    auto load_chunk = [&](int kc, int st) {
        const uint32_t sa = smb + st*2*HTSZ;
        const uint32_t sb = sa + HTSZ;
        #pragma unroll
        for (int i = 0; i < 4; i++) {
            const int a   = tid + i*256;
            const int row = a >> 3;
            const int ca  = a & 7;
            const uint32_t doff = (uint32_t)(row*HPITCH + ca*8) * 2;
            CP_ASYNC16(sa + doff, gA + (size_t)row*AGGK + kc*GBK + ca*8);
            CP_ASYNC16(sb + doff, gB + (size_t)row*AGGK + kc*GBK + ca*8);
        }
        CP_COMMIT();
    };

    const int a_r  = (lane & 7) + ((lane >> 3) & 1) * 8;
    const int a_ka = lane >> 4;
    const int b_r  = (lane & 7) + (lane >> 4) * 8;
    const int b_ka = (lane >> 3) & 1;

    float acc[4][4][4];
    #pragma unroll
    for (int mf = 0; mf < 4; mf++)
        #pragma unroll
        for (int nf = 0; nf < 4; nf++)
            #pragma unroll
            for (int i = 0; i < 4; i++) acc[mf][nf][i] = 0.f;

    load_chunk(0, 0);

    for (int kc = 0; kc < NCH; kc++) {
        if (kc + 1 < NCH) {
            load_chunk(kc + 1, (kc + 1) & 1);
            CP_WAIT1();
        } else {
            CP_WAIT0();
        }
        __syncthreads();

        const uint32_t sa = smb + (kc & 1)*2*HTSZ;
        const uint32_t sb = sa + HTSZ;

        #pragma unroll 4
        for (int ks = 0; ks < 4; ks++) {
            uint32_t a[4][4], bb[4][2];
            #pragma unroll
            for (int mf = 0; mf < 4; mf++) {
                uint32_t addr = sa + (uint32_t)((m0 + mf*16 + a_r)*HPITCH
                                + (ks*2 + a_ka)*8) * 2;
                ldsm_x4(a[mf][0], a[mf][1], a[mf][2], a[mf][3], addr);
            }
            #pragma unroll
            for (int np = 0; np < 2; np++) {
                uint32_t addr = sb + (uint32_t)((n0 + np*16 + b_r)*HPITCH
                                + (ks*2 + b_ka)*8) * 2;
                ldsm_x4(bb[np*2][0], bb[np*2][1], bb[np*2+1][0], bb[np*2+1][1], addr);
            }
            #pragma unroll
            for (int mf = 0; mf < 4; mf++)
                #pragma unroll
                for (int nf = 0; nf < 4; nf++)
                    mma_f16(acc[mf][nf], a[mf], bb[nf]);
        }
        __syncthreads();
    }

    const float inv_k = 1.0f / (float)KNB;
    #pragma unroll
    for (int mf = 0; mf < 4; mf++) {
        const int row = p0 + m0 + mf*16 + g;
        #pragma unroll
        for (int nf = 0; nf < 4; nf++) {
            const int col = n0 + nf*8 + t4*2;
            const float b0 = sbias[col], b1 = sbias[col+1];
            float2 v0 = make_float2(acc[mf][nf][0]*inv_k + b0, acc[mf][nf][1]*inv_k + b1);
            float2 v1 = make_float2(acc[mf][nf][2]*inv_k + b0, acc[mf][nf][3]*inv_k + b1);
            *(float2*)(out + (size_t)row*COUT + col)     = v0;
            *(float2*)(out + (size_t)(row+8)*COUT + col) = v1;
        }
    }
}

// ============================================================
__global__ void copy_pts_kernel(const float* __restrict__ src, float* __restrict__ dst)
{
    int i = blockIdx.x * blockDim.x + threadIdx.x;
    const int n4 = (NPTS * 3) / 4;
    if (i < n4) ((float4*)dst)[i] = ((const float4*)src)[i];
}

// ============================================================
extern "C" void kernel_launch(void* const* d_in, const int* in_sizes, int n_in,
                              void* d_out, int out_size)
{
    const float* features   = (const float*)d_in[0];
    const float* input_pts  = (const float*)d_in[1];
    const float* output_pts = (const float*)d_in[2];
    const int*   indices    = (const int*)  d_in[3];
    const float* centers    = (const float*)d_in[4];
    const float* weight     = (const float*)d_in[5];
    const float* bias       = (const float*)d_in[6];
    const float* l1_w       = (const float*)d_in[7];
    const float* l1_b       = (const float*)d_in[8];
    const float* l2_w       = (const float*)d_in[9];
    const float* l2_b       = (const float*)d_in[10];
    const float* l3_w       = (const float*)d_in[11];
    const float* l3_b       = (const float*)d_in[12];

    float* out = (float*)d_out;

    cudaFuncSetAttribute(gemm_mma_kernel,
                         cudaFuncAttributeMaxDynamicSharedMemorySize, GEMM_SMEM);

    prep_kernel<<<1, 32>>>(l1_w, l1_b, centers);
    permw_kernel<<<(AGGK*COUT + 255)/256, 256>>>(weight);
    agg_kernel<<<NPTS/8, 128>>>(features, input_pts, output_pts, indices,
                                l2_w, l2_b, l3_w, l3_b);
    gemm_mma_kernel<<<NPTS/128, 256, GEMM_SMEM>>>(bias, out);

    if (out_size >= NPTS*COUT + NPTS*3) {
        copy_pts_kernel<<<(NPTS*3/4 + 255)/256, 256>>>(output_pts, out + (size_t)NPTS*COUT);
    }
}